// round 10
// baseline (speedup 1.0000x reference)
#include <cuda_runtime.h>

// out[i,p] = sum_{m,n} A[i,m] * B[i,n] * C[m,n,p]   (M1=M2=MP=5)
//
// Round-10 = round-8 base (constant-bank C, direct strided IO, 64-reg cap,
// 4 CTAs/SM = 32 warps — the proven no-spill config) with two changes:
//  (1) EPT 2 -> 4: per-thread span is 80B so A and B load as 5x LDG.128 each,
//      ALL front-batched -> 2x outstanding loads per warp. Rounds 3/8 showed
//      latency exposure (nothing saturated, warps capped at 32); MLP is the
//      only remaining lever.
//  (2) C pad-transposed in constant (cCp[m][p][8]) so each column is
//      LDC.128 + LDC.32 (2 issues, not 5) — keeps total issue slots in
//      budget at the doubled edge count. (Round 9 showed this is fine; its
//      regression was the 48-reg spill, not the LDC.128.)
// Compute is pair-sequential (edges {0,1} then {2,3}) with per-pair stores
// so peak live regs ~63 < 64 — ptxas can serialize instead of spilling.

#define M1 5
#define M2 5
#define MP 5
#define EPT 4
#define TPB 256
#define CPAD_FLOATS (M1 * MP * 8)      // 200

__constant__ float cCp[CPAD_FLOATS];   // cCp[(m*5+p)*8 + n], n in 0..4, padded
__device__ float g_scratch[CPAD_FLOATS];

__global__ void transpose_C_kernel(const float* __restrict__ C) {
    int idx = threadIdx.x;             // one block of 256 covers 200 slots
    if (idx < CPAD_FLOATS) {
        int m   = idx / (MP * 8);
        int rem = idx % (MP * 8);
        int p   = rem / 8;
        int n   = rem % 8;
        g_scratch[idx] = (n < M2) ? C[(m * M2 + n) * MP + p] : 0.0f;
    }
}

__global__ __launch_bounds__(TPB, 4)
void cg_combine_kernel(const float* __restrict__ A,
                       const float* __restrict__ B,
                       float* __restrict__ out,
                       long long n_edges)
{
    int t = threadIdx.x;
    long long tid = (long long)blockIdx.x * TPB + t;
    long long e0  = tid * EPT;

    if (e0 + EPT <= n_edges) {
        size_t base = (size_t)e0 * 5;        // 20 floats = 80B, 16B-aligned

        // ---- front-batched loads: 10x LDG.128, max MLP ----
        const float4* A4 = reinterpret_cast<const float4*>(A + base);
        const float4* B4 = reinterpret_cast<const float4*>(B + base);
        float4 va[5], vb[5];
#pragma unroll
        for (int i = 0; i < 5; i++) va[i] = __ldcs(A4 + i);
#pragma unroll
        for (int i = 0; i < 5; i++) vb[i] = __ldcs(B4 + i);

        // flat views: a[j] = j-th float of the 20 (edge j/5, comp j%5)
        float a[20], b[20];
#pragma unroll
        for (int i = 0; i < 5; i++) {
            a[4*i+0] = va[i].x; a[4*i+1] = va[i].y;
            a[4*i+2] = va[i].z; a[4*i+3] = va[i].w;
            b[4*i+0] = vb[i].x; b[4*i+1] = vb[i].y;
            b[4*i+2] = vb[i].z; b[4*i+3] = vb[i].w;
        }

        float2* O2 = reinterpret_cast<float2*>(out + base);

        // ---- two sequential pairs: keeps acc live-set at 10, not 20 ----
#pragma unroll
        for (int h = 0; h < 2; h++) {
            const int ea = 10 * h;           // flat offset of edge 2h
            const int eb = 10 * h + 5;       // flat offset of edge 2h+1

            float acc[10];                   // [0..4]=edge2h, [5..9]=edge2h+1
#pragma unroll
            for (int i = 0; i < 10; i++) acc[i] = 0.0f;

#pragma unroll
            for (int m = 0; m < M1; m++) {
                float am0 = a[ea + m];
                float am1 = a[eb + m];
#pragma unroll
                for (int p = 0; p < MP; p++) {
                    // C column (m, :, p): LDC.128 + LDC.32 (padded constant)
                    const float4 c03 =
                        *reinterpret_cast<const float4*>(&cCp[(m * MP + p) * 8]);
                    const float  c4  = cCp[(m * MP + p) * 8 + 4];

                    float d0 = c03.x * b[ea + 0];
                    float d1 = c03.x * b[eb + 0];
                    d0 = fmaf(b[ea + 1], c03.y, d0);
                    d1 = fmaf(b[eb + 1], c03.y, d1);
                    d0 = fmaf(b[ea + 2], c03.z, d0);
                    d1 = fmaf(b[eb + 2], c03.z, d1);
                    d0 = fmaf(b[ea + 3], c03.w, d0);
                    d1 = fmaf(b[eb + 3], c03.w, d1);
                    d0 = fmaf(b[ea + 4], c4,    d0);
                    d1 = fmaf(b[eb + 4], c4,    d1);

                    acc[p]     = fmaf(am0, d0, acc[p]);
                    acc[5 + p] = fmaf(am1, d1, acc[5 + p]);
                }
            }

            // store this pair's 10 floats (5x STG.64), freeing acc regs
#pragma unroll
            for (int i = 0; i < 5; i++)
                __stcs(O2 + 5 * h + i, make_float2(acc[2*i], acc[2*i+1]));
        }
    } else if (e0 < n_edges) {
        // ---- tail path (scalar; not taken for N = 16,777,216) ----
        for (long long e = e0; e < n_edges; e++) {
            float a[5], b[5];
#pragma unroll
            for (int k = 0; k < 5; k++) { a[k] = A[e * 5 + k]; b[k] = B[e * 5 + k]; }
#pragma unroll
            for (int p = 0; p < MP; p++) {
                float s = 0.0f;
#pragma unroll
                for (int m = 0; m < M1; m++) {
                    float d = 0.0f;
#pragma unroll
                    for (int n = 0; n < M2; n++)
                        d = fmaf(b[n], cCp[(m * MP + p) * 8 + n], d);
                    s = fmaf(a[m], d, s);
                }
                out[e * 5 + p] = s;
            }
        }
    }
}

extern "C" void kernel_launch(void* const* d_in, const int* in_sizes, int n_in,
                              void* d_out, int out_size)
{
    const float* A = (const float*)d_in[0];
    const float* B = (const float*)d_in[1];
    const float* C = (const float*)d_in[2];
    float* out = (float*)d_out;

    // Prep: pad-transpose C into __device__ scratch, then copy into the
    // constant bank. Both are graph-capturable stream-0 nodes; stream order
    // guarantees the main kernel sees finished constant data.
    transpose_C_kernel<<<1, TPB>>>(C);
    void* scratch_ptr = nullptr;
    cudaGetSymbolAddress(&scratch_ptr, g_scratch);
    cudaMemcpyToSymbolAsync(cCp, scratch_ptr, CPAD_FLOATS * sizeof(float), 0,
                            cudaMemcpyDeviceToDevice, 0);

    long long n_edges = (long long)in_sizes[0] / M1;
    long long n_threads = (n_edges + EPT - 1) / EPT;
    int blocks = (int)((n_threads + TPB - 1) / TPB);

    cg_combine_kernel<<<blocks, TPB>>>(A, B, out, n_edges);
}

// round 11
// speedup vs baseline: 1.4673x; 1.4673x over previous
#include <cuda_runtime.h>

// out[i,p] = sum_{m,n} A[i,m] * B[i,n] * C[m,n,p]   (M1=M2=MP=5)
//
// Round-11: EPT=1 to honestly shrink the live set (~30 regs) and buy warps.
//  - __launch_bounds__(256,6): 42-reg cap -> 6 CTAs/SM = 48 warps (+50%
//    latency coverage over round-8's 32). Rounds 4/5/9/10 proved bigger
//    per-thread state spills at any cap; EPT=1 is the config with real slack.
//  - L1tex wavefronts/edge are footprint-invariant under EPT (strided lane
//    pattern covers the same unique lines), so no wavefront penalty.
//  - C pad-transposed in constant: each (m,:,p) column = LDC.128 + LDC.32
//    (uniform-const port, off the L1 crossbar), 2 issues instead of 5.

#define M1 5
#define M2 5
#define MP 5
#define TPB 256
#define CPAD_FLOATS (M1 * MP * 8)      // 200

__constant__ float cCp[CPAD_FLOATS];   // cCp[(m*5+p)*8 + n], n in 0..4, padded
__device__ float g_scratch[CPAD_FLOATS];

__global__ void transpose_C_kernel(const float* __restrict__ C) {
    int idx = threadIdx.x;             // one block of 256 covers 200 slots
    if (idx < CPAD_FLOATS) {
        int m   = idx / (MP * 8);
        int rem = idx % (MP * 8);
        int p   = rem / 8;
        int n   = rem % 8;
        g_scratch[idx] = (n < M2) ? C[(m * M2 + n) * MP + p] : 0.0f;
    }
}

__global__ __launch_bounds__(TPB, 6)
void cg_combine_kernel(const float* __restrict__ A,
                       const float* __restrict__ B,
                       float* __restrict__ out,
                       long long n_edges)
{
    long long e = (long long)blockIdx.x * TPB + threadIdx.x;
    if (e >= n_edges) return;

    size_t base = (size_t)e * 5;

    // ---- front-batched loads: 10x LDG.32 ----
    const float* pa = A + base;
    const float* pb = B + base;
    float a0 = __ldcs(pa + 0), a1 = __ldcs(pa + 1), a2 = __ldcs(pa + 2),
          a3 = __ldcs(pa + 3), a4 = __ldcs(pa + 4);
    float b0 = __ldcs(pb + 0), b1 = __ldcs(pb + 1), b2 = __ldcs(pb + 2),
          b3 = __ldcs(pb + 3), b4 = __ldcs(pb + 4);

    float acc[MP];
#pragma unroll
    for (int p = 0; p < MP; p++) acc[p] = 0.0f;

    float am;
#pragma unroll
    for (int m = 0; m < M1; m++) {
        switch (m) {                    // keep a* as scalars, not an array
            case 0: am = a0; break;
            case 1: am = a1; break;
            case 2: am = a2; break;
            case 3: am = a3; break;
            default: am = a4; break;
        }
#pragma unroll
        for (int p = 0; p < MP; p++) {
            // C column (m, :, p): LDC.128 + LDC.32 from padded constant
            const float4 c03 =
                *reinterpret_cast<const float4*>(&cCp[(m * MP + p) * 8]);
            const float  c4  = cCp[(m * MP + p) * 8 + 4];

            float d = c03.x * b0;
            d = fmaf(b1, c03.y, d);
            d = fmaf(b2, c03.z, d);
            d = fmaf(b3, c03.w, d);
            d = fmaf(b4, c4,    d);

            acc[p] = fmaf(am, d, acc[p]);
        }
    }

    float* po = out + base;
#pragma unroll
    for (int p = 0; p < MP; p++) __stcs(po + p, acc[p]);
}

extern "C" void kernel_launch(void* const* d_in, const int* in_sizes, int n_in,
                              void* d_out, int out_size)
{
    const float* A = (const float*)d_in[0];
    const float* B = (const float*)d_in[1];
    const float* C = (const float*)d_in[2];
    float* out = (float*)d_out;

    // Prep: pad-transpose C into __device__ scratch, then copy into the
    // constant bank. Graph-capturable stream-0 nodes; stream order makes the
    // constant data visible to the main kernel.
    transpose_C_kernel<<<1, TPB>>>(C);
    void* scratch_ptr = nullptr;
    cudaGetSymbolAddress(&scratch_ptr, g_scratch);
    cudaMemcpyToSymbolAsync(cCp, scratch_ptr, CPAD_FLOATS * sizeof(float), 0,
                            cudaMemcpyDeviceToDevice, 0);

    long long n_edges = (long long)in_sizes[0] / M1;
    int blocks = (int)((n_edges + TPB - 1) / TPB);

    cg_combine_kernel<<<blocks, TPB>>>(A, B, out, n_edges);
}